// round 12
// baseline (speedup 1.0000x reference)
#include <cuda_runtime.h>

#define ND 128
#define HID 16
#define N_MAX 100000

typedef unsigned long long u64;

// Device-global scratch; statically zeroed; each run restores its own state
// so graph replays see identical initial conditions.
__device__ __align__(16) int g_udi[N_MAX];   // cnt*2^24 + sum(s*2^16); reset by node_kernel
__device__ __align__(16) int g_si[N_MAX];    // per-node fixed-point: 2^24 + round(s*2^16)
__device__ float    g_acc;                   // reset by last node_kernel block
__device__ unsigned g_done;                  // wraps via atomicInc

#define FMA2(d, a, b) \
    asm("fma.rn.f32x2 %0, %1, %2, %3;" : "=l"(d) : "l"(a), "l"(b), "l"(d))
#define PACK2(d, s) \
    asm("mov.b64 %0, {%1, %1};" : "=l"(d) : "r"(__float_as_uint(s)))
#define UNPACK2(lo, hi, s) \
    asm("mov.b64 {%0, %1}, %2;" : "=r"(lo), "=r"(hi) : "l"(s))

__device__ __forceinline__ float ftanh(float v) {
    return 1.0f - __fdividef(2.0f, __expf(2.0f * v) + 1.0f);
}

// ---------------- K1: MLP -> s_fixed, pipelined smem-staged x, NPT=1 -------
#define MLP_TPB 128
#define NB 128                    // nodes per block
#define KT 8                      // 8 k-tiles of 16 floats (4 float4)

__global__ void __launch_bounds__(MLP_TPB) mlp_kernel(
    const float* __restrict__ x,
    const float* __restrict__ W1, const float* __restrict__ b1,
    const float* __restrict__ W2, const float* __restrict__ b2,
    const float* __restrict__ W3, const float* __restrict__ b3,
    const float* __restrict__ Wc,
    int n)
{
    __shared__ float4 sX[NB * 5];          // 128 rows x (4 float4 + 1 pad) = 10.25KB
    __shared__ float4 sW1[ND * HID / 4];   // 8KB
    __shared__ float4 sW2[HID * HID / 4];
    __shared__ float4 sW3[HID * HID / 4];
    __shared__ u64 sb1[8], sb2[8], sb3[8];
    __shared__ float sWc[HID];

    int tid = threadIdx.x;
    for (int i = tid; i < ND * HID / 4; i += MLP_TPB) sW1[i] = ((const float4*)W1)[i];
    if (tid < HID * HID / 4) {
        sW2[tid] = ((const float4*)W2)[tid];
        sW3[tid] = ((const float4*)W3)[tid];
    }
    if (tid < 8) {
        sb1[tid] = ((const u64*)b1)[tid];
        sb2[tid] = ((const u64*)b2)[tid];
        sb3[tid] = ((const u64*)b3)[tid];
    }
    if (tid < HID) sWc[tid] = Wc[tid];

    int nodeBase = blockIdx.x * NB;
    int myN0 = min(nodeBase + tid, n - 1);

    // cooperative-load coordinates (fixed across tiles): 4 float4 per thread
    int lr[4], lj[4];
    const float4* lg[4];
#pragma unroll
    for (int i = 0; i < 4; i++) {
        int lin = i * MLP_TPB + tid;
        lr[i] = lin >> 2;
        lj[i] = lin & 3;
        int gn = min(nodeBase + lr[i], n - 1);
        lg[i] = ((const float4*)(x + (size_t)gn * ND)) + lj[i];
    }

    u64 h[8];

    // prologue: issue loads for tile 0
    float4 v[4];
#pragma unroll
    for (int i = 0; i < 4; i++) v[i] = lg[i][0];

    __syncthreads();  // weights + biases visible
#pragma unroll
    for (int q = 0; q < 8; q++) h[q] = sb1[q];

    // ---- layer 1 over 8 k-tiles of 16 floats, software-pipelined ----
#pragma unroll
    for (int kt = 0; kt < KT; kt++) {
        if (kt > 0) __syncthreads();  // previous tile fully consumed by all
#pragma unroll
        for (int i = 0; i < 4; i++) sX[lr[i] * 5 + lj[i]] = v[i];  // waits on v
        __syncthreads();

        // issue next tile's loads NOW; latency hidden behind this tile's FMAs
        if (kt + 1 < KT) {
#pragma unroll
            for (int i = 0; i < 4; i++) v[i] = lg[i][(kt + 1) * 4];
        }

#pragma unroll
        for (int j = 0; j < 4; j++) {
            float4 xa = sX[tid * 5 + j];
            float xas[4] = {xa.x, xa.y, xa.z, xa.w};
#pragma unroll
            for (int i = 0; i < 4; i++) {
                int k = kt * 16 + j * 4 + i;
                const ulonglong2* wr = (const ulonglong2*)(sW1 + k * 4);
                u64 xp;
                PACK2(xp, xas[i]);
#pragma unroll
                for (int q = 0; q < 4; q++) {
                    ulonglong2 ww = wr[q];
                    FMA2(h[2 * q],     xp, ww.x);
                    FMA2(h[2 * q + 1], xp, ww.y);
                }
            }
        }
    }

    float t0[HID];
#pragma unroll
    for (int q = 0; q < 8; q++) {
        unsigned lo, hi;
        UNPACK2(lo, hi, h[q]);
        t0[2 * q]     = ftanh(__uint_as_float(lo));
        t0[2 * q + 1] = ftanh(__uint_as_float(hi));
    }

    // ---- layer 2 ----
    u64 a0[8];
#pragma unroll
    for (int q = 0; q < 8; q++) a0[q] = sb2[q];
#pragma unroll
    for (int i = 0; i < HID; i++) {
        const ulonglong2* wr = (const ulonglong2*)(sW2 + i * 4);
        u64 p0;
        PACK2(p0, t0[i]);
#pragma unroll
        for (int q = 0; q < 4; q++) {
            ulonglong2 ww = wr[q];
            FMA2(a0[2 * q],     p0, ww.x);
            FMA2(a0[2 * q + 1], p0, ww.y);
        }
    }
#pragma unroll
    for (int q = 0; q < 8; q++) {
        unsigned lo, hi;
        UNPACK2(lo, hi, a0[q]);
        t0[2 * q]     = ftanh(__uint_as_float(lo));
        t0[2 * q + 1] = ftanh(__uint_as_float(hi));
    }

    // ---- layer 3 ----
#pragma unroll
    for (int q = 0; q < 8; q++) a0[q] = sb3[q];
#pragma unroll
    for (int i = 0; i < HID; i++) {
        const ulonglong2* wr = (const ulonglong2*)(sW3 + i * 4);
        u64 p0;
        PACK2(p0, t0[i]);
#pragma unroll
        for (int q = 0; q < 4; q++) {
            ulonglong2 ww = wr[q];
            FMA2(a0[2 * q],     p0, ww.x);
            FMA2(a0[2 * q + 1], p0, ww.y);
        }
    }

    // tanh + contract with Wc -> scalar; store fixed-point 2^24 + s*2^16
    float s0 = 0.f;
#pragma unroll
    for (int q = 0; q < 8; q++) {
        unsigned lo, hi;
        UNPACK2(lo, hi, a0[q]);
        s0 += ftanh(__uint_as_float(lo)) * sWc[2 * q];
        s0 += ftanh(__uint_as_float(hi)) * sWc[2 * q + 1];
    }
    // clamped duplicate writes carry identical values -> benign
    g_si[myN0] = (1 << 24) + __float2int_rn(s0 * 65536.0f);
}

// ------ K2: single edge pass: udi[src] += si[dst]  (one RED.ADD.32) -------
#define E_TPB 256
#define E_EPT 8

__global__ void __launch_bounds__(E_TPB) edge_kernel(
    const int* __restrict__ src, const int* __restrict__ dst, int e)
{
    long base = (long)(blockIdx.x * E_TPB + threadIdx.x) * E_EPT;
    if (base + E_EPT <= e) {
        int4 da = *(const int4*)(dst + base);
        int4 db = *(const int4*)(dst + base + 4);
        int4 sa = *(const int4*)(src + base);
        int4 sb = *(const int4*)(src + base + 4);
        int v0 = __ldg(&g_si[da.x]), v1 = __ldg(&g_si[da.y]);
        int v2 = __ldg(&g_si[da.z]), v3 = __ldg(&g_si[da.w]);
        int v4 = __ldg(&g_si[db.x]), v5 = __ldg(&g_si[db.y]);
        int v6 = __ldg(&g_si[db.z]), v7 = __ldg(&g_si[db.w]);
        atomicAdd(&g_udi[sa.x], v0);
        atomicAdd(&g_udi[sa.y], v1);
        atomicAdd(&g_udi[sa.z], v2);
        atomicAdd(&g_udi[sa.w], v3);
        atomicAdd(&g_udi[sb.x], v4);
        atomicAdd(&g_udi[sb.y], v5);
        atomicAdd(&g_udi[sb.z], v6);
        atomicAdd(&g_udi[sb.w], v7);
    } else {
        for (long i = base; i < e; i++)
            atomicAdd(&g_udi[src[i]], __ldg(&g_si[dst[i]]));
    }
}

// ------ K3: node pass: acc = sum_m u[m]/cnt[m]; sigmoid; reset state ------
#define N_TPB 256

__global__ void __launch_bounds__(N_TPB) node_kernel(
    const float* __restrict__ bc, float* __restrict__ out, int n, float inv_n)
{
    __shared__ float sRed[N_TPB / 32];
    int tid = threadIdx.x;
    int i = blockIdx.x * N_TPB + tid;
    float term = 0.f;

    if (i < n) {
        int v = g_udi[i];
        if (v != 0) {
            // cnt = round(v / 2^24); |fraction| < 2^23 so rounding recovers cnt
            int cnt = (v + (1 << 23)) >> 24;
            float u = (float)(v - (cnt << 24)) * (1.0f / 65536.0f);
            term = u * __frcp_rn((float)cnt);
            g_udi[i] = 0;  // restore for next graph replay
        }
    }

    unsigned m = 0xffffffffu;
#pragma unroll
    for (int off = 16; off > 0; off >>= 1)
        term += __shfl_down_sync(m, term, off);
    if ((tid & 31) == 0) sRed[tid >> 5] = term;
    __syncthreads();

    if (tid == 0) {
        float v = 0.f;
#pragma unroll
        for (int wq = 0; wq < N_TPB / 32; wq++) v += sRed[wq];
        atomicAdd(&g_acc, v);
        __threadfence();
        unsigned ticket = atomicInc(&g_done, gridDim.x - 1);  // wraps to 0 on last
        if (ticket == gridDim.x - 1) {
            float z = g_acc * inv_n + bc[0];
            out[0] = 1.0f / (1.0f + __expf(-z));
            g_acc = 0.f;  // restore for next replay
        }
    }
}

extern "C" void kernel_launch(void* const* d_in, const int* in_sizes, int n_in,
                              void* d_out, int out_size) {
    const float* x    = (const float*)d_in[0];
    const int*   esrc = (const int*)  d_in[1];
    const int*   edst = (const int*)  d_in[2];
    const float* W1   = (const float*)d_in[3];
    const float* b1   = (const float*)d_in[4];
    const float* W2   = (const float*)d_in[5];
    const float* b2   = (const float*)d_in[6];
    const float* W3   = (const float*)d_in[7];
    const float* b3   = (const float*)d_in[8];
    const float* Wc   = (const float*)d_in[9];
    const float* bc   = (const float*)d_in[10];
    float* out = (float*)d_out;

    int n = in_sizes[0] / ND;
    int e = in_sizes[1];
    if (n > N_MAX) n = N_MAX;

    int nMlp = (n + NB - 1) / NB;
    mlp_kernel<<<nMlp, MLP_TPB>>>(x, W1, b1, W2, b2, W3, b3, Wc, n);

    int nEdge = (e + E_TPB * E_EPT - 1) / (E_TPB * E_EPT);
    edge_kernel<<<nEdge, E_TPB>>>(esrc, edst, e);

    int nNode = (n + N_TPB - 1) / N_TPB;
    node_kernel<<<nNode, N_TPB>>>(bc, out, n, 1.0f / (float)n);
}

// round 13
// speedup vs baseline: 1.1210x; 1.1210x over previous
#include <cuda_runtime.h>

#define ND 128
#define HID 16
#define N_MAX 100000

typedef unsigned long long u64;

// Device-global scratch; statically zeroed; each run restores its own state
// so graph replays see identical initial conditions.
__device__ __align__(16) int g_udi[N_MAX];   // cnt*2^24 + sum(s*2^16); reset by node_kernel
__device__ __align__(16) int g_si[N_MAX];    // per-node fixed-point: 2^24 + round(s*2^16)
__device__ float    g_acc;                   // reset by last node_kernel block
__device__ unsigned g_done;                  // wraps via atomicInc

#define FMA2(d, a, b) \
    asm("fma.rn.f32x2 %0, %1, %2, %3;" : "=l"(d) : "l"(a), "l"(b), "l"(d))
#define PACK2(d, s) \
    asm("mov.b64 %0, {%1, %1};" : "=l"(d) : "r"(__float_as_uint(s)))
#define UNPACK2(lo, hi, s) \
    asm("mov.b64 {%0, %1}, %2;" : "=r"(lo), "=r"(hi) : "l"(s))
#define CP16(d, s) \
    asm volatile("cp.async.ca.shared.global [%0], [%1], 16;" :: "r"(d), "l"(s))
#define CP_COMMIT() asm volatile("cp.async.commit_group;")

__device__ __forceinline__ float ftanh(float v) {
    return 1.0f - __fdividef(2.0f, __expf(2.0f * v) + 1.0f);
}

// ------- K1: MLP -> s_fixed, cp.async double-buffered x staging, NPT=2 -----
#define MLP_TPB 128
#define MLP_NPT 2                 // 256 nodes per block
#define NB (MLP_TPB * MLP_NPT)    // 256
#define KT 8                      // 8 k-tiles of 16 floats (4 float4 per row)
#define TILE_B (NB * 5 * 16)      // bytes per sX stage

__global__ void __launch_bounds__(MLP_TPB) mlp_kernel(
    const float* __restrict__ x,
    const float* __restrict__ W1, const float* __restrict__ b1,
    const float* __restrict__ W2, const float* __restrict__ b2,
    const float* __restrict__ W3, const float* __restrict__ b3,
    const float* __restrict__ Wc,
    int n)
{
    __shared__ float4 sX[2][NB * 5];       // 2 stages x 256 rows x (4 f4 + pad) = 41KB
    __shared__ float4 sW1[ND * HID / 4];   // 8KB
    __shared__ float4 sW2[HID * HID / 4];
    __shared__ float4 sW3[HID * HID / 4];
    __shared__ u64 sb1[8], sb2[8], sb3[8];
    __shared__ float sWc[HID];

    int tid = threadIdx.x;
    int nodeBase = blockIdx.x * NB;

    // cooperative-load coordinates (fixed across tiles): 8 16B chunks/thread
    const char* lgp[8];
    unsigned dsto[8];
#pragma unroll
    for (int i = 0; i < 8; i++) {
        int lin = i * MLP_TPB + tid;
        int lr = lin >> 2;
        int lj = lin & 3;
        int gn = min(nodeBase + lr, n - 1);
        lgp[i] = (const char*)(x + (size_t)gn * ND) + lj * 16;
        dsto[i] = (unsigned)(lr * 5 + lj) * 16u;
    }
    unsigned sxb = (unsigned)__cvta_generic_to_shared(&sX[0][0]);

    // prologue: 2-deep prefetch (tiles 0 and 1)
#pragma unroll
    for (int i = 0; i < 8; i++) CP16(sxb + dsto[i], lgp[i]);
    CP_COMMIT();
#pragma unroll
    for (int i = 0; i < 8; i++) CP16(sxb + TILE_B + dsto[i], lgp[i] + 64);
    CP_COMMIT();

    // weights + biases
    for (int i = tid; i < ND * HID / 4; i += MLP_TPB) sW1[i] = ((const float4*)W1)[i];
    if (tid < HID * HID / 4) {
        sW2[tid] = ((const float4*)W2)[tid];
        sW3[tid] = ((const float4*)W3)[tid];
    }
    if (tid < 8) {
        sb1[tid] = ((const u64*)b1)[tid];
        sb2[tid] = ((const u64*)b2)[tid];
        sb3[tid] = ((const u64*)b3)[tid];
    }
    if (tid < HID) sWc[tid] = Wc[tid];

    int r0 = tid, r1 = tid + MLP_TPB;
    int myN0 = min(nodeBase + r0, n - 1);
    int myN1 = min(nodeBase + r1, n - 1);

    __syncthreads();  // weights visible

    u64 h0[8], h1v[8];
#pragma unroll
    for (int q = 0; q < 8; q++) { h0[q] = sb1[q]; h1v[q] = sb1[q]; }

    // ---- layer 1 over 8 k-tiles, cp.async pipelined 2 deep ----
#pragma unroll
    for (int kt = 0; kt < KT; kt++) {
        if (kt < KT - 1) {
            asm volatile("cp.async.wait_group 1;");
        } else {
            asm volatile("cp.async.wait_group 0;");
        }
        __syncthreads();  // tile kt visible to all

        const float4* buf = sX[kt & 1];
#pragma unroll
        for (int j = 0; j < 4; j++) {
            float4 xa = buf[r0 * 5 + j];
            float4 xb = buf[r1 * 5 + j];
            float xas[4] = {xa.x, xa.y, xa.z, xa.w};
            float xbs[4] = {xb.x, xb.y, xb.z, xb.w};
#pragma unroll
            for (int i = 0; i < 4; i++) {
                int k = kt * 16 + j * 4 + i;
                const ulonglong2* wr = (const ulonglong2*)(sW1 + k * 4);
                u64 xpa, xpb;
                PACK2(xpa, xas[i]);
                PACK2(xpb, xbs[i]);
#pragma unroll
                for (int q = 0; q < 4; q++) {
                    ulonglong2 ww = wr[q];
                    FMA2(h0[2 * q],      xpa, ww.x);
                    FMA2(h0[2 * q + 1],  xpa, ww.y);
                    FMA2(h1v[2 * q],     xpb, ww.x);
                    FMA2(h1v[2 * q + 1], xpb, ww.y);
                }
            }
        }
        __syncthreads();  // all done reading buf before refill

        if (kt + 2 < KT) {
            unsigned stage = (unsigned)(kt & 1) * TILE_B;
#pragma unroll
            for (int i = 0; i < 8; i++)
                CP16(sxb + stage + dsto[i], lgp[i] + (kt + 2) * 64);
            CP_COMMIT();
        }
    }

    float t0[HID], t1[HID];
#pragma unroll
    for (int q = 0; q < 8; q++) {
        unsigned lo, hi;
        UNPACK2(lo, hi, h0[q]);
        t0[2 * q] = ftanh(__uint_as_float(lo));
        t0[2 * q + 1] = ftanh(__uint_as_float(hi));
        UNPACK2(lo, hi, h1v[q]);
        t1[2 * q] = ftanh(__uint_as_float(lo));
        t1[2 * q + 1] = ftanh(__uint_as_float(hi));
    }

    // ---- layer 2 ----
    u64 a0[8], a1[8];
#pragma unroll
    for (int q = 0; q < 8; q++) { a0[q] = sb2[q]; a1[q] = sb2[q]; }
#pragma unroll
    for (int i = 0; i < HID; i++) {
        const ulonglong2* wr = (const ulonglong2*)(sW2 + i * 4);
        u64 p0, p1;
        PACK2(p0, t0[i]);
        PACK2(p1, t1[i]);
#pragma unroll
        for (int q = 0; q < 4; q++) {
            ulonglong2 ww = wr[q];
            FMA2(a0[2 * q],     p0, ww.x);
            FMA2(a0[2 * q + 1], p0, ww.y);
            FMA2(a1[2 * q],     p1, ww.x);
            FMA2(a1[2 * q + 1], p1, ww.y);
        }
    }
#pragma unroll
    for (int q = 0; q < 8; q++) {
        unsigned lo, hi;
        UNPACK2(lo, hi, a0[q]);
        t0[2 * q] = ftanh(__uint_as_float(lo));
        t0[2 * q + 1] = ftanh(__uint_as_float(hi));
        UNPACK2(lo, hi, a1[q]);
        t1[2 * q] = ftanh(__uint_as_float(lo));
        t1[2 * q + 1] = ftanh(__uint_as_float(hi));
    }

    // ---- layer 3 ----
#pragma unroll
    for (int q = 0; q < 8; q++) { a0[q] = sb3[q]; a1[q] = sb3[q]; }
#pragma unroll
    for (int i = 0; i < HID; i++) {
        const ulonglong2* wr = (const ulonglong2*)(sW3 + i * 4);
        u64 p0, p1;
        PACK2(p0, t0[i]);
        PACK2(p1, t1[i]);
#pragma unroll
        for (int q = 0; q < 4; q++) {
            ulonglong2 ww = wr[q];
            FMA2(a0[2 * q],     p0, ww.x);
            FMA2(a0[2 * q + 1], p0, ww.y);
            FMA2(a1[2 * q],     p1, ww.x);
            FMA2(a1[2 * q + 1], p1, ww.y);
        }
    }

    // tanh + contract with Wc -> fixed-point scalar per node
    float s0 = 0.f, s1 = 0.f;
#pragma unroll
    for (int q = 0; q < 8; q++) {
        unsigned lo, hi;
        UNPACK2(lo, hi, a0[q]);
        s0 += ftanh(__uint_as_float(lo)) * sWc[2 * q];
        s0 += ftanh(__uint_as_float(hi)) * sWc[2 * q + 1];
        UNPACK2(lo, hi, a1[q]);
        s1 += ftanh(__uint_as_float(lo)) * sWc[2 * q];
        s1 += ftanh(__uint_as_float(hi)) * sWc[2 * q + 1];
    }
    // clamped duplicate writes carry identical values -> benign
    g_si[myN0] = (1 << 24) + __float2int_rn(s0 * 65536.0f);
    g_si[myN1] = (1 << 24) + __float2int_rn(s1 * 65536.0f);
}

// ------ K2: single edge pass: udi[src] += si[dst]  (one RED.ADD.32) -------
#define E_TPB 256
#define E_EPT 8

__global__ void __launch_bounds__(E_TPB) edge_kernel(
    const int* __restrict__ src, const int* __restrict__ dst, int e)
{
    long base = (long)(blockIdx.x * E_TPB + threadIdx.x) * E_EPT;
    if (base + E_EPT <= e) {
        int4 da = *(const int4*)(dst + base);
        int4 db = *(const int4*)(dst + base + 4);
        int4 sa = *(const int4*)(src + base);
        int4 sb = *(const int4*)(src + base + 4);
        int v0 = __ldg(&g_si[da.x]), v1 = __ldg(&g_si[da.y]);
        int v2 = __ldg(&g_si[da.z]), v3 = __ldg(&g_si[da.w]);
        int v4 = __ldg(&g_si[db.x]), v5 = __ldg(&g_si[db.y]);
        int v6 = __ldg(&g_si[db.z]), v7 = __ldg(&g_si[db.w]);
        atomicAdd(&g_udi[sa.x], v0);
        atomicAdd(&g_udi[sa.y], v1);
        atomicAdd(&g_udi[sa.z], v2);
        atomicAdd(&g_udi[sa.w], v3);
        atomicAdd(&g_udi[sb.x], v4);
        atomicAdd(&g_udi[sb.y], v5);
        atomicAdd(&g_udi[sb.z], v6);
        atomicAdd(&g_udi[sb.w], v7);
    } else {
        for (long i = base; i < e; i++)
            atomicAdd(&g_udi[src[i]], __ldg(&g_si[dst[i]]));
    }
}

// ------ K3: node pass: acc = sum_m u[m]/cnt[m]; sigmoid; reset state ------
#define N_TPB 256

__global__ void __launch_bounds__(N_TPB) node_kernel(
    const float* __restrict__ bc, float* __restrict__ out, int n, float inv_n)
{
    __shared__ float sRed[N_TPB / 32];
    int tid = threadIdx.x;
    int i = blockIdx.x * N_TPB + tid;
    float term = 0.f;

    if (i < n) {
        int v = g_udi[i];
        if (v != 0) {
            // cnt = round(v / 2^24); |fraction| < 2^23 so rounding recovers cnt
            int cnt = (v + (1 << 23)) >> 24;
            float u = (float)(v - (cnt << 24)) * (1.0f / 65536.0f);
            term = u * __frcp_rn((float)cnt);
            g_udi[i] = 0;  // restore for next graph replay
        }
    }

    unsigned m = 0xffffffffu;
#pragma unroll
    for (int off = 16; off > 0; off >>= 1)
        term += __shfl_down_sync(m, term, off);
    if ((tid & 31) == 0) sRed[tid >> 5] = term;
    __syncthreads();

    if (tid == 0) {
        float v = 0.f;
#pragma unroll
        for (int wq = 0; wq < N_TPB / 32; wq++) v += sRed[wq];
        atomicAdd(&g_acc, v);
        __threadfence();
        unsigned ticket = atomicInc(&g_done, gridDim.x - 1);  // wraps to 0 on last
        if (ticket == gridDim.x - 1) {
            float z = g_acc * inv_n + bc[0];
            out[0] = 1.0f / (1.0f + __expf(-z));
            g_acc = 0.f;  // restore for next replay
        }
    }
}

extern "C" void kernel_launch(void* const* d_in, const int* in_sizes, int n_in,
                              void* d_out, int out_size) {
    const float* x    = (const float*)d_in[0];
    const int*   esrc = (const int*)  d_in[1];
    const int*   edst = (const int*)  d_in[2];
    const float* W1   = (const float*)d_in[3];
    const float* b1   = (const float*)d_in[4];
    const float* W2   = (const float*)d_in[5];
    const float* b2   = (const float*)d_in[6];
    const float* W3   = (const float*)d_in[7];
    const float* b3   = (const float*)d_in[8];
    const float* Wc   = (const float*)d_in[9];
    const float* bc   = (const float*)d_in[10];
    float* out = (float*)d_out;

    int n = in_sizes[0] / ND;
    int e = in_sizes[1];
    if (n > N_MAX) n = N_MAX;

    int nMlp = (n + NB - 1) / NB;
    mlp_kernel<<<nMlp, MLP_TPB>>>(x, W1, b1, W2, b2, W3, b3, Wc, n);

    int nEdge = (e + E_TPB * E_EPT - 1) / (E_TPB * E_EPT);
    edge_kernel<<<nEdge, E_TPB>>>(esrc, edst, e);

    int nNode = (n + N_TPB - 1) / N_TPB;
    node_kernel<<<nNode, N_TPB>>>(bc, out, n, 1.0f / (float)n);
}